// round 1
// baseline (speedup 1.0000x reference)
#include <cuda_runtime.h>
#include <math.h>

// Problem constants
#define TT    2048
#define HH    16
#define NOPE  128
#define ROPE  64
#define DQK   192           // NOPE + ROPE
#define LORA  512
#define VDIM  128
#define QKSCALE 0.07216878364870323f   // 1/sqrt(192)

// Attention tiling
#define BQ   64
#define BKV  64
#define PQK  193            // padded row stride for Q/K smem (odd -> 2-way max conflict)
#define PP   68             // padded row stride for P smem

// Scratch (no cudaMalloc allowed): K_nope and V in [H][T][*] layout
__device__ float g_K[HH * TT * NOPE];   // 16 MB
__device__ float g_V[HH * TT * VDIM];   // 16 MB

// ---------------------------------------------------------------------------
// Stage 1: C(2048 x 4096) = k_c(2048 x 512) @ B(512 x 4096)
// where col j: h = j/256, r = j%256;
//   r < 128  -> B[l][j] = w_kv_b[l][h*256 + r]      (K_nope)
//   r >= 128 -> B[l][j] = w_uv[h][l][r-128]         (V = k_c @ w_uv[h])
// ---------------------------------------------------------------------------
__global__ __launch_bounds__(256) void kv_gemm_kernel(
    const float* __restrict__ kc,
    const float* __restrict__ wkv,
    const float* __restrict__ wuv)
{
    __shared__ float As[64][33];
    __shared__ float Bs[32][68];

    const int bm = blockIdx.y * 64;   // t tile
    const int bn = blockIdx.x * 64;   // output col tile
    const int tid = threadIdx.x;
    const int tx = tid & 15;
    const int ty = tid >> 4;

    float acc[4][4];
#pragma unroll
    for (int i = 0; i < 4; i++)
#pragma unroll
        for (int j = 0; j < 4; j++) acc[i][j] = 0.f;

    for (int kt = 0; kt < LORA; kt += 32) {
        // Load A tile 64x32 (coalesced: 32 consecutive cols per row)
#pragma unroll
        for (int i = 0; i < 8; i++) {
            int idx = tid + i * 256;
            int r = idx >> 5, c = idx & 31;
            As[r][c] = kc[(bm + r) * LORA + kt + c];
        }
        // Load B tile 32x64 (branch is uniform per block: bn is 64-aligned)
#pragma unroll
        for (int i = 0; i < 8; i++) {
            int idx = tid + i * 256;
            int r = idx >> 6, c = idx & 63;
            int j = bn + c;
            int h  = j >> 8;
            int rr = j & 255;
            int l  = kt + r;
            float v;
            if (rr < NOPE) v = wkv[l * (HH * 256) + h * 256 + rr];
            else           v = wuv[(h * LORA + l) * VDIM + (rr - NOPE)];
            Bs[r][c] = v;
        }
        __syncthreads();

#pragma unroll
        for (int k = 0; k < 32; k++) {
            float a[4];
#pragma unroll
            for (int i = 0; i < 4; i++) a[i] = As[ty * 4 + i][k];
            float4 bv = *(const float4*)&Bs[k][tx * 4];
            float b[4] = {bv.x, bv.y, bv.z, bv.w};
#pragma unroll
            for (int i = 0; i < 4; i++)
#pragma unroll
                for (int j = 0; j < 4; j++) acc[i][j] += a[i] * b[j];
        }
        __syncthreads();
    }

    // Store to split destinations
#pragma unroll
    for (int i = 0; i < 4; i++) {
        int t = bm + ty * 4 + i;
#pragma unroll
        for (int j = 0; j < 4; j++) {
            int jg = bn + tx * 4 + j;
            int h  = jg >> 8;
            int rr = jg & 255;
            if (rr < NOPE) g_K[(h * TT + t) * NOPE + rr]          = acc[i][j];
            else           g_V[(h * TT + t) * VDIM + (rr - NOPE)] = acc[i][j];
        }
    }
}

// ---------------------------------------------------------------------------
// Stage 2: causal flash attention, fp32 SIMT.
// Block = (q-tile of 64, head). 256 threads (16x16).
// Each thread: S micro-tile 4x4, O micro-tile 4x8 (rows ty*4+i, cols tx*8+j).
// ---------------------------------------------------------------------------
__global__ __launch_bounds__(256, 1) void attn_kernel(
    const float* __restrict__ query,
    const float* __restrict__ kpe,
    float* __restrict__ out)
{
    extern __shared__ float sm[];
    float* Qs     = sm;                    // BQ  * PQK
    float* Ks     = Qs + BQ * PQK;         // BKV * PQK
    float* Vs     = Ks + BKV * PQK;        // BKV * VDIM
    float* Ps     = Vs + BKV * VDIM;       // BQ  * PP
    float* row_m  = Ps + BQ * PP;          // BQ
    float* row_l  = row_m + BQ;            // BQ
    float* row_sc = row_l + BQ;            // BQ

    const int h  = blockIdx.y;
    const int q0 = blockIdx.x * BQ;
    const int tid = threadIdx.x;
    const int tx = tid & 15;
    const int ty = tid >> 4;

    // Load Q tile (rope part comes directly with query layout (T,H,192))
    for (int idx = tid; idx < BQ * DQK; idx += 256) {
        int r = idx / DQK, c = idx - r * DQK;
        Qs[r * PQK + c] = query[((q0 + r) * HH + h) * DQK + c];
    }
    if (tid < BQ) { row_m[tid] = -INFINITY; row_l[tid] = 0.f; }

    float o[4][8];
#pragma unroll
    for (int i = 0; i < 4; i++)
#pragma unroll
        for (int j = 0; j < 8; j++) o[i][j] = 0.f;

    const int ntile = q0 / BKV + 1;   // causal: only tiles with s0 <= q0

    for (int kt = 0; kt < ntile; kt++) {
        const int s0 = kt * BKV;
        __syncthreads();   // previous iteration's PV reads done before overwrite

        // Load K tile: nope cols from g_K, rope cols straight from k_pe
        for (int idx = tid; idx < BKV * DQK; idx += 256) {
            int r = idx / DQK, c = idx - r * DQK;
            float v = (c < NOPE) ? g_K[(h * TT + s0 + r) * NOPE + c]
                                 : kpe[(s0 + r) * ROPE + (c - NOPE)];
            Ks[r * PQK + c] = v;
        }
        // Load V tile
        for (int idx = tid; idx < BKV * VDIM; idx += 256) {
            int r = idx >> 7, c = idx & 127;
            Vs[r * VDIM + c] = g_V[(h * TT + s0 + r) * VDIM + c];
        }
        __syncthreads();

        // S = Q @ K^T  (4x4 per thread)
        float s[4][4];
#pragma unroll
        for (int i = 0; i < 4; i++)
#pragma unroll
            for (int j = 0; j < 4; j++) s[i][j] = 0.f;

#pragma unroll 4
        for (int d = 0; d < DQK; d++) {
            float a[4], b[4];
#pragma unroll
            for (int i = 0; i < 4; i++) a[i] = Qs[(ty * 4 + i) * PQK + d];
#pragma unroll
            for (int j = 0; j < 4; j++) b[j] = Ks[(tx * 4 + j) * PQK + d];
#pragma unroll
            for (int i = 0; i < 4; i++)
#pragma unroll
                for (int j = 0; j < 4; j++) s[i][j] += a[i] * b[j];
        }

        // Scale + causal mask, write raw logits to Ps
#pragma unroll
        for (int i = 0; i < 4; i++) {
            int rq = q0 + ty * 4 + i;
#pragma unroll
            for (int j = 0; j < 4; j++) {
                int cs = s0 + tx * 4 + j;
                float val = (cs <= rq) ? s[i][j] * QKSCALE : -1.0e30f;
                Ps[(ty * 4 + i) * PP + tx * 4 + j] = val;
            }
        }
        __syncthreads();

        // Online softmax update: one thread per row
        if (tid < BQ) {
            const int r = tid;
            float tmax = -1.0e30f;
            for (int c = 0; c < BKV; c++) tmax = fmaxf(tmax, Ps[r * PP + c]);
            float m_old = row_m[r];
            float m_new = fmaxf(m_old, tmax);
            float sc = (m_old == -INFINITY) ? 0.f : __expf(m_old - m_new);
            float lsum = 0.f;
            for (int c = 0; c < BKV; c++) {
                float p = __expf(Ps[r * PP + c] - m_new);
                Ps[r * PP + c] = p;
                lsum += p;
            }
            row_l[r] = row_l[r] * sc + lsum;
            row_m[r] = m_new;
            row_sc[r] = sc;
        }
        __syncthreads();

        // O = O * sc + P @ V
        float scs[4];
#pragma unroll
        for (int i = 0; i < 4; i++) scs[i] = row_sc[ty * 4 + i];
#pragma unroll
        for (int i = 0; i < 4; i++)
#pragma unroll
            for (int j = 0; j < 8; j++) o[i][j] *= scs[i];

#pragma unroll 2
        for (int k = 0; k < BKV; k++) {
            float p[4];
#pragma unroll
            for (int i = 0; i < 4; i++) p[i] = Ps[(ty * 4 + i) * PP + k];
            float4 v0 = *(const float4*)&Vs[k * VDIM + tx * 8];
            float4 v1 = *(const float4*)&Vs[k * VDIM + tx * 8 + 4];
#pragma unroll
            for (int i = 0; i < 4; i++) {
                o[i][0] += p[i] * v0.x;  o[i][1] += p[i] * v0.y;
                o[i][2] += p[i] * v0.z;  o[i][3] += p[i] * v0.w;
                o[i][4] += p[i] * v1.x;  o[i][5] += p[i] * v1.y;
                o[i][6] += p[i] * v1.z;  o[i][7] += p[i] * v1.w;
            }
        }
    }

    // Epilogue: normalize and store (out layout (T, H*VDIM))
    float linv[4];
#pragma unroll
    for (int i = 0; i < 4; i++) linv[i] = 1.0f / row_l[ty * 4 + i];

#pragma unroll
    for (int i = 0; i < 4; i++) {
        int t = q0 + ty * 4 + i;
        float4 r0, r1;
        r0.x = o[i][0] * linv[i]; r0.y = o[i][1] * linv[i];
        r0.z = o[i][2] * linv[i]; r0.w = o[i][3] * linv[i];
        r1.x = o[i][4] * linv[i]; r1.y = o[i][5] * linv[i];
        r1.z = o[i][6] * linv[i]; r1.w = o[i][7] * linv[i];
        float* dst = out + t * (HH * VDIM) + h * VDIM + tx * 8;
        *(float4*)dst       = r0;
        *(float4*)(dst + 4) = r1;
    }
}

// ---------------------------------------------------------------------------
extern "C" void kernel_launch(void* const* d_in, const int* in_sizes, int n_in,
                              void* d_out, int out_size)
{
    const float* query = (const float*)d_in[0];  // (T, H, 192)
    const float* kc    = (const float*)d_in[1];  // (T, 512)
    const float* kpe   = (const float*)d_in[2];  // (T, 64)
    const float* wkv   = (const float*)d_in[3];  // (512, 4096)
    const float* wuv   = (const float*)d_in[4];  // (16, 512, 128)
    float* out = (float*)d_out;                  // (T, 2048)

    // Stage 1: K_nope and V
    kv_gemm_kernel<<<dim3(64, 32), 256>>>(kc, wkv, wuv);

    // Stage 2: flash attention
    size_t smem = (size_t)(BQ * PQK + BKV * PQK + BKV * VDIM + BQ * PP + 3 * BQ)
                  * sizeof(float);  // ~146 KB
    cudaFuncSetAttribute(attn_kernel,
                         cudaFuncAttributeMaxDynamicSharedMemorySize, (int)smem);
    attn_kernel<<<dim3(TT / BQ, HH), 256, smem>>>(query, kpe, out);
}

// round 5
// speedup vs baseline: 1.1603x; 1.1603x over previous
#include <cuda_runtime.h>
#include <math.h>

// Problem constants
#define TT    2048
#define HH    16
#define NOPE  128
#define ROPE  64
#define DQK   192
#define LORA  512
#define VDIM  128
#define QKSCALE 0.07216878364870323f   // 1/sqrt(192)

// Attention tiling
#define BQ   64
#define BKV  64
#define QSTR 196    // Qs/Ks row stride (192+4): frag-load bank = 4g+q, conflict-free
#define VSTR 136    // Vs row stride (128+8): frag-load bank = 8q+g, conflict-free
#define PSTR 68     // P row stride (64+4):  frag-load bank = 4g+q, conflict-free

// Scratch: K_nope and V in [H][T][*] layout
__device__ float g_K[HH * TT * NOPE];   // 16 MB
__device__ float g_V[HH * TT * VDIM];   // 16 MB

// ---------------------------------------------------------------------------
// Stage 1: C(2048 x 4096) = k_c(2048 x 512) @ B(512 x 4096)  (fp32, exact)
// ---------------------------------------------------------------------------
__global__ __launch_bounds__(256) void kv_gemm_kernel(
    const float* __restrict__ kc,
    const float* __restrict__ wkv,
    const float* __restrict__ wuv)
{
    __shared__ float As[64][33];
    __shared__ float Bs[32][68];

    const int bm = blockIdx.y * 64;
    const int bn = blockIdx.x * 64;
    const int tid = threadIdx.x;
    const int tx = tid & 15;
    const int ty = tid >> 4;

    float acc[4][4];
#pragma unroll
    for (int i = 0; i < 4; i++)
#pragma unroll
        for (int j = 0; j < 4; j++) acc[i][j] = 0.f;

    for (int kt = 0; kt < LORA; kt += 32) {
#pragma unroll
        for (int i = 0; i < 8; i++) {
            int idx = tid + i * 256;
            int r = idx >> 5, c = idx & 31;
            As[r][c] = kc[(bm + r) * LORA + kt + c];
        }
#pragma unroll
        for (int i = 0; i < 8; i++) {
            int idx = tid + i * 256;
            int r = idx >> 6, c = idx & 63;
            int j = bn + c;
            int h  = j >> 8;
            int rr = j & 255;
            int l  = kt + r;
            float v;
            if (rr < NOPE) v = wkv[l * (HH * 256) + h * 256 + rr];
            else           v = wuv[(h * LORA + l) * VDIM + (rr - NOPE)];
            Bs[r][c] = v;
        }
        __syncthreads();

#pragma unroll
        for (int k = 0; k < 32; k++) {
            float a[4];
#pragma unroll
            for (int i = 0; i < 4; i++) a[i] = As[ty * 4 + i][k];
            float4 bv = *(const float4*)&Bs[k][tx * 4];
            float b[4] = {bv.x, bv.y, bv.z, bv.w};
#pragma unroll
            for (int i = 0; i < 4; i++)
#pragma unroll
                for (int j = 0; j < 4; j++) acc[i][j] += a[i] * b[j];
        }
        __syncthreads();
    }

#pragma unroll
    for (int i = 0; i < 4; i++) {
        int t = bm + ty * 4 + i;
#pragma unroll
        for (int j = 0; j < 4; j++) {
            int jg = bn + tx * 4 + j;
            int h  = jg >> 8;
            int rr = jg & 255;
            if (rr < NOPE) g_K[(h * TT + t) * NOPE + rr]          = acc[i][j];
            else           g_V[(h * TT + t) * VDIM + (rr - NOPE)] = acc[i][j];
        }
    }
}

// ---------------------------------------------------------------------------
// tf32 helpers
// ---------------------------------------------------------------------------
__device__ __forceinline__ unsigned f2tf(float f) {
    unsigned u;
    asm("cvt.rna.tf32.f32 %0, %1;" : "=r"(u) : "f"(f));
    return u;
}

__device__ __forceinline__ void mma_tf32(float* c,
    unsigned a0, unsigned a1, unsigned a2, unsigned a3,
    unsigned b0, unsigned b1)
{
    asm volatile(
        "mma.sync.aligned.m16n8k8.row.col.f32.tf32.tf32.f32 "
        "{%0,%1,%2,%3}, {%4,%5,%6,%7}, {%8,%9}, {%0,%1,%2,%3};\n"
        : "+f"(c[0]), "+f"(c[1]), "+f"(c[2]), "+f"(c[3])
        : "r"(a0), "r"(a1), "r"(a2), "r"(a3), "r"(b0), "r"(b1));
}

// ---------------------------------------------------------------------------
// Stage 2: causal flash attention with tf32 MMA (FA-2 style).
// 128 threads = 4 warps; warp w owns q-rows [w*16, w*16+16) of a 64-row tile.
// ---------------------------------------------------------------------------
__global__ __launch_bounds__(128, 1) void attn_kernel(
    const float* __restrict__ query,
    const float* __restrict__ kpe,
    float* __restrict__ out)
{
    extern __shared__ unsigned sm[];
    unsigned* Qs = sm;                       // 64 * QSTR
    unsigned* Ks = Qs + BQ * QSTR;           // 64 * QSTR
    unsigned* Vs = Ks + BKV * QSTR;          // 64 * VSTR
    unsigned* Ps = Vs + BKV * VSTR;          // 4 * 16 * PSTR (warp-private)

    const int h    = blockIdx.y;
    const int qt   = (int)gridDim.x - 1 - (int)blockIdx.x;  // heavy tiles first
    const int q0   = qt * BQ;
    const int tid  = threadIdx.x;
    const int w    = tid >> 5;
    const int lane = tid & 31;
    const int g    = lane >> 2;   // group id 0..7
    const int q    = lane & 3;    // thread-in-group 0..3
    unsigned* Pw   = Ps + w * 16 * PSTR;

    // Load Q tile (tf32-converted)
    for (int idx = tid; idx < BQ * DQK; idx += 128) {
        int r = idx / DQK, c = idx - r * DQK;
        Qs[r * QSTR + c] = f2tf(query[((q0 + r) * HH + h) * DQK + c]);
    }

    float oAcc[16][4];
#pragma unroll
    for (int n = 0; n < 16; n++)
#pragma unroll
        for (int i = 0; i < 4; i++) oAcc[n][i] = 0.f;

    float m_lo = -INFINITY, m_hi = -INFINITY;
    float l_lo = 0.f, l_hi = 0.f;

    const int row_lo = q0 + w * 16 + g;
    const int row_hi = row_lo + 8;
    const int ntile  = qt + 1;

    for (int kt = 0; kt < ntile; kt++) {
        const int s0 = kt * BKV;
        __syncthreads();   // Q ready (iter 0) / prev iter done reading K,V

        // Load K tile: nope from g_K, rope from k_pe
        for (int idx = tid; idx < BKV * DQK; idx += 128) {
            int r = idx / DQK, c = idx - r * DQK;
            float v = (c < NOPE) ? g_K[(h * TT + s0 + r) * NOPE + c]
                                 : kpe[(s0 + r) * ROPE + (c - NOPE)];
            Ks[r * QSTR + c] = f2tf(v);
        }
        // Load V tile
        for (int idx = tid; idx < BKV * VDIM; idx += 128) {
            int r = idx >> 7, c = idx & 127;
            Vs[r * VSTR + c] = f2tf(g_V[(h * TT + s0 + r) * VDIM + c]);
        }
        __syncthreads();

        // ---- S = Q @ K^T via mma (8 n-tiles of 16x8, 24 k-steps) ----
        float sA[8][4];
#pragma unroll
        for (int n = 0; n < 8; n++)
#pragma unroll
            for (int i = 0; i < 4; i++) sA[n][i] = 0.f;

#pragma unroll
        for (int kb = 0; kb < DQK / 8; kb++) {
            const int k0 = kb * 8;
            unsigned a0 = Qs[(w * 16 + g    ) * QSTR + k0 + q    ];
            unsigned a1 = Qs[(w * 16 + g + 8) * QSTR + k0 + q    ];
            unsigned a2 = Qs[(w * 16 + g    ) * QSTR + k0 + q + 4];
            unsigned a3 = Qs[(w * 16 + g + 8) * QSTR + k0 + q + 4];
#pragma unroll
            for (int n = 0; n < 8; n++) {
                unsigned b0 = Ks[(n * 8 + g) * QSTR + k0 + q    ];
                unsigned b1 = Ks[(n * 8 + g) * QSTR + k0 + q + 4];
                mma_tf32(sA[n], a0, a1, a2, a3, b0, b1);
            }
        }

        // ---- scale + causal mask (in registers) ----
#pragma unroll
        for (int n = 0; n < 8; n++) {
            int c0 = s0 + n * 8 + 2 * q;
            sA[n][0] = (c0     <= row_lo) ? sA[n][0] * QKSCALE : -1.0e30f;
            sA[n][1] = (c0 + 1 <= row_lo) ? sA[n][1] * QKSCALE : -1.0e30f;
            sA[n][2] = (c0     <= row_hi) ? sA[n][2] * QKSCALE : -1.0e30f;
            sA[n][3] = (c0 + 1 <= row_hi) ? sA[n][3] * QKSCALE : -1.0e30f;
        }

        // ---- online softmax, fully in registers (quad reductions) ----
        float tm_lo = -1.0e30f, tm_hi = -1.0e30f;
#pragma unroll
        for (int n = 0; n < 8; n++) {
            tm_lo = fmaxf(tm_lo, fmaxf(sA[n][0], sA[n][1]));
            tm_hi = fmaxf(tm_hi, fmaxf(sA[n][2], sA[n][3]));
        }
        tm_lo = fmaxf(tm_lo, __shfl_xor_sync(0xffffffffu, tm_lo, 1));
        tm_lo = fmaxf(tm_lo, __shfl_xor_sync(0xffffffffu, tm_lo, 2));
        tm_hi = fmaxf(tm_hi, __shfl_xor_sync(0xffffffffu, tm_hi, 1));
        tm_hi = fmaxf(tm_hi, __shfl_xor_sync(0xffffffffu, tm_hi, 2));

        float mn_lo = fmaxf(m_lo, tm_lo);
        float mn_hi = fmaxf(m_hi, tm_hi);
        float sc_lo = __expf(m_lo - mn_lo);   // exp(-inf)=0 on first tile
        float sc_hi = __expf(m_hi - mn_hi);

        float sum_lo = 0.f, sum_hi = 0.f;
#pragma unroll
        for (int n = 0; n < 8; n++) {
            sA[n][0] = __expf(sA[n][0] - mn_lo);
            sA[n][1] = __expf(sA[n][1] - mn_lo);
            sA[n][2] = __expf(sA[n][2] - mn_hi);
            sA[n][3] = __expf(sA[n][3] - mn_hi);
            sum_lo += sA[n][0] + sA[n][1];
            sum_hi += sA[n][2] + sA[n][3];
        }
        sum_lo += __shfl_xor_sync(0xffffffffu, sum_lo, 1);
        sum_lo += __shfl_xor_sync(0xffffffffu, sum_lo, 2);
        sum_hi += __shfl_xor_sync(0xffffffffu, sum_hi, 1);
        sum_hi += __shfl_xor_sync(0xffffffffu, sum_hi, 2);

        l_lo = l_lo * sc_lo + sum_lo;  m_lo = mn_lo;
        l_hi = l_hi * sc_hi + sum_hi;  m_hi = mn_hi;

        // Rescale O accumulators
#pragma unroll
        for (int n = 0; n < 16; n++) {
            oAcc[n][0] *= sc_lo;  oAcc[n][1] *= sc_lo;
            oAcc[n][2] *= sc_hi;  oAcc[n][3] *= sc_hi;
        }

        // ---- write P (tf32) into warp-private smem for PV A-operand ----
        __syncwarp();
#pragma unroll
        for (int n = 0; n < 8; n++) {
            uint2 plo = make_uint2(f2tf(sA[n][0]), f2tf(sA[n][1]));
            uint2 phi = make_uint2(f2tf(sA[n][2]), f2tf(sA[n][3]));
            *(uint2*)&Pw[(g    ) * PSTR + n * 8 + 2 * q] = plo;
            *(uint2*)&Pw[(g + 8) * PSTR + n * 8 + 2 * q] = phi;
        }
        __syncwarp();

        // ---- O += P @ V via mma (16 n-tiles of 16x8, 8 k-steps) ----
#pragma unroll
        for (int kb = 0; kb < BKV / 8; kb++) {
            const int k0 = kb * 8;
            unsigned a0 = Pw[(g    ) * PSTR + k0 + q    ];
            unsigned a1 = Pw[(g + 8) * PSTR + k0 + q    ];
            unsigned a2 = Pw[(g    ) * PSTR + k0 + q + 4];
            unsigned a3 = Pw[(g + 8) * PSTR + k0 + q + 4];
#pragma unroll
            for (int n = 0; n < 16; n++) {
                unsigned b0 = Vs[(k0 + q    ) * VSTR + n * 8 + g];
                unsigned b1 = Vs[(k0 + q + 4) * VSTR + n * 8 + g];
                mma_tf32(oAcc[n], a0, a1, a2, a3, b0, b1);
            }
        }
    }

    // ---- epilogue: normalize + store ----
    const float il_lo = 1.0f / l_lo;
    const float il_hi = 1.0f / l_hi;
    const int t_lo = row_lo;
    const int t_hi = row_hi;
#pragma unroll
    for (int n = 0; n < 16; n++) {
        int col = h * VDIM + n * 8 + 2 * q;
        float2 vlo = make_float2(oAcc[n][0] * il_lo, oAcc[n][1] * il_lo);
        float2 vhi = make_float2(oAcc[n][2] * il_hi, oAcc[n][3] * il_hi);
        *(float2*)&out[t_lo * (HH * VDIM) + col] = vlo;
        *(float2*)&out[t_hi * (HH * VDIM) + col] = vhi;
    }
}

// ---------------------------------------------------------------------------
extern "C" void kernel_launch(void* const* d_in, const int* in_sizes, int n_in,
                              void* d_out, int out_size)
{
    const float* query = (const float*)d_in[0];  // (T, H, 192)
    const float* kc    = (const float*)d_in[1];  // (T, 512)
    const float* kpe   = (const float*)d_in[2];  // (T, 64)
    const float* wkv   = (const float*)d_in[3];  // (512, 4096)
    const float* wuv   = (const float*)d_in[4];  // (16, 512, 128)
    float* out = (float*)d_out;                  // (T, 2048)

    kv_gemm_kernel<<<dim3(64, 32), 256>>>(kc, wkv, wuv);

    size_t smem = (size_t)(BQ * QSTR + BKV * QSTR + BKV * VSTR + 4 * 16 * PSTR)
                  * sizeof(unsigned);   // ~149 KB
    cudaFuncSetAttribute(attn_kernel,
                         cudaFuncAttributeMaxDynamicSharedMemorySize, (int)smem);
    attn_kernel<<<dim3(TT / BQ, HH), 128, smem>>>(query, kpe, out);
}

// round 6
// speedup vs baseline: 3.2351x; 2.7881x over previous
#include <cuda_runtime.h>
#include <math.h>

// Problem constants
#define TT    2048
#define HH    16
#define NOPE  128
#define ROPE  64
#define DQK   192
#define LORA  512
#define VDIM  128
#define QKSCALE 0.07216878364870323f   // 1/sqrt(192)

// Attention tiling
#define BQ   128
#define BKV  64
#define NWARP 8
#define QSTR 196    // Qs/Ks row stride (192+4): frag-load bank = 4g+q, conflict-free
#define VSTR 136    // Vs row stride (128+8): frag-load bank = 8q+g, conflict-free
#define PSTR 68     // P  row stride (64+4):  frag-load bank = 4g+q, conflict-free

// Scratch: K (nope+rope, tf32-rounded, per head) and V (tf32-rounded)
__device__ float g_K[HH * TT * DQK];    // 25 MB
__device__ float g_V[HH * TT * VDIM];   // 16 MB

// ---------------------------------------------------------------------------
// tf32 + cp.async helpers
// ---------------------------------------------------------------------------
__device__ __forceinline__ unsigned f2tf(float f) {
    unsigned u;
    asm("cvt.rna.tf32.f32 %0, %1;" : "=r"(u) : "f"(f));
    return u;
}

#define CP16(dst_u32, src_ptr) \
    asm volatile("cp.async.cg.shared.global [%0], [%1], 16;\n" \
                 :: "r"(dst_u32), "l"(src_ptr))
#define CP_COMMIT() asm volatile("cp.async.commit_group;\n" ::)
#define CP_WAIT1()  asm volatile("cp.async.wait_group 1;\n" ::)

__device__ __forceinline__ void mma_tf32(float* c,
    unsigned a0, unsigned a1, unsigned a2, unsigned a3,
    unsigned b0, unsigned b1)
{
    asm volatile(
        "mma.sync.aligned.m16n8k8.row.col.f32.tf32.tf32.f32 "
        "{%0,%1,%2,%3}, {%4,%5,%6,%7}, {%8,%9}, {%0,%1,%2,%3};\n"
        : "+f"(c[0]), "+f"(c[1]), "+f"(c[2]), "+f"(c[3])
        : "r"(a0), "r"(a1), "r"(a2), "r"(a3), "r"(b0), "r"(b1));
}

// ---------------------------------------------------------------------------
// Stage 1: C(2048 x 4096) = k_c(2048 x 512) @ B(512 x 4096), fp32 accum,
// output tf32-rounded into g_K (nope cols, stride DQK) / g_V.
// ---------------------------------------------------------------------------
__global__ __launch_bounds__(256) void kv_gemm_kernel(
    const float* __restrict__ kc,
    const float* __restrict__ wkv,
    const float* __restrict__ wuv)
{
    __shared__ float As[64][33];
    __shared__ float Bs[32][68];

    const int bm = blockIdx.y * 64;
    const int bn = blockIdx.x * 64;
    const int tid = threadIdx.x;
    const int tx = tid & 15;
    const int ty = tid >> 4;

    float acc[4][4];
#pragma unroll
    for (int i = 0; i < 4; i++)
#pragma unroll
        for (int j = 0; j < 4; j++) acc[i][j] = 0.f;

    for (int kt = 0; kt < LORA; kt += 32) {
#pragma unroll
        for (int i = 0; i < 8; i++) {
            int idx = tid + i * 256;
            int r = idx >> 5, c = idx & 31;
            As[r][c] = kc[(bm + r) * LORA + kt + c];
        }
#pragma unroll
        for (int i = 0; i < 8; i++) {
            int idx = tid + i * 256;
            int r = idx >> 6, c = idx & 63;
            int j = bn + c;
            int h  = j >> 8;
            int rr = j & 255;
            int l  = kt + r;
            float v;
            if (rr < NOPE) v = wkv[l * (HH * 256) + h * 256 + rr];
            else           v = wuv[(h * LORA + l) * VDIM + (rr - NOPE)];
            Bs[r][c] = v;
        }
        __syncthreads();

#pragma unroll
        for (int k = 0; k < 32; k++) {
            float a[4];
#pragma unroll
            for (int i = 0; i < 4; i++) a[i] = As[ty * 4 + i][k];
            float4 bv = *(const float4*)&Bs[k][tx * 4];
            float b[4] = {bv.x, bv.y, bv.z, bv.w};
#pragma unroll
            for (int i = 0; i < 4; i++)
#pragma unroll
                for (int j = 0; j < 4; j++) acc[i][j] += a[i] * b[j];
        }
        __syncthreads();
    }

#pragma unroll
    for (int i = 0; i < 4; i++) {
        int t = bm + ty * 4 + i;
#pragma unroll
        for (int j = 0; j < 4; j++) {
            int jg = bn + tx * 4 + j;
            int h  = jg >> 8;
            int rr = jg & 255;
            float v = __uint_as_float(f2tf(acc[i][j]));
            if (rr < NOPE) g_K[((size_t)(h * TT + t)) * DQK + rr]          = v;
            else           g_V[((size_t)(h * TT + t)) * VDIM + (rr - NOPE)] = v;
        }
    }
}

// ---------------------------------------------------------------------------
// Rope fill: replicate k_pe into g_K cols [128,192) for every head (tf32).
// ---------------------------------------------------------------------------
__global__ __launch_bounds__(256) void rope_fill_kernel(const float* __restrict__ kpe)
{
    int idx = blockIdx.x * 256 + threadIdx.x;       // H*T*ROPE elements
    if (idx >= HH * TT * ROPE) return;
    int h   = idx / (TT * ROPE);
    int rem = idx - h * (TT * ROPE);
    int t   = rem / ROPE;
    int c   = rem - t * ROPE;
    g_K[((size_t)(h * TT + t)) * DQK + NOPE + c] =
        __uint_as_float(f2tf(kpe[t * ROPE + c]));
}

// ---------------------------------------------------------------------------
// Stage 2: causal flash attention, tf32 MMA, 8 warps, cp.async pipelined.
// Warp w owns q-rows [w*16, w*16+16) of a 128-row q-tile.
// ---------------------------------------------------------------------------
__global__ __launch_bounds__(256, 1) void attn_kernel(
    const float* __restrict__ query,
    float* __restrict__ out)
{
    extern __shared__ unsigned sm[];
    unsigned* Qs = sm;                       // BQ  * QSTR
    unsigned* Ks = Qs + BQ * QSTR;           // BKV * QSTR
    unsigned* Vs = Ks + BKV * QSTR;          // BKV * VSTR
    unsigned* Ps = Vs + BKV * VSTR;          // NWARP * 16 * PSTR

    const int h    = blockIdx.y;
    const int qt   = (int)gridDim.x - 1 - (int)blockIdx.x;  // heavy tiles first
    const int q0   = qt * BQ;
    const int tid  = threadIdx.x;
    const int w    = tid >> 5;
    const int lane = tid & 31;
    const int g    = lane >> 2;
    const int q    = lane & 3;
    unsigned* Pw   = Ps + w * 16 * PSTR;

    const unsigned Ks_u = (unsigned)__cvta_generic_to_shared(Ks);
    const unsigned Vs_u = (unsigned)__cvta_generic_to_shared(Vs);

    const float* gKh = g_K + (size_t)h * TT * DQK;
    const float* gVh = g_V + (size_t)h * TT * VDIM;

    const int ntile = 2 * qt + 2;

    // ---- prologue: Q load (tf32) + first K/V cp.async ----
    for (int idx = tid; idx < BQ * 48; idx += 256) {
        int r = idx / 48, cw = idx - r * 48;
        float4 v = *(const float4*)&query[((size_t)(q0 + r) * HH + h) * DQK + cw * 4];
        unsigned* d = &Qs[r * QSTR + cw * 4];
        d[0] = f2tf(v.x); d[1] = f2tf(v.y); d[2] = f2tf(v.z); d[3] = f2tf(v.w);
    }
    {   // K tile 0
        const float* base = gKh;
#pragma unroll
        for (int i = 0; i < 12; i++) {
            int idx = tid + i * 256;
            int r = idx / 48, cw = idx - r * 48;
            CP16(Ks_u + (unsigned)(r * QSTR + cw * 4) * 4u, base + r * DQK + cw * 4);
        }
        CP_COMMIT();
    }
    {   // V tile 0
        const float* base = gVh;
#pragma unroll
        for (int i = 0; i < 8; i++) {
            int idx = tid + i * 256;
            int r = idx >> 5, cw = idx & 31;
            CP16(Vs_u + (unsigned)(r * VSTR + cw * 4) * 4u, base + r * VDIM + cw * 4);
        }
        CP_COMMIT();
    }

    float oAcc[16][4];
#pragma unroll
    for (int n = 0; n < 16; n++)
#pragma unroll
        for (int i = 0; i < 4; i++) oAcc[n][i] = 0.f;

    float m_lo = -INFINITY, m_hi = -INFINITY;
    float l_lo = 0.f, l_hi = 0.f;

    const int row_lo   = q0 + w * 16 + g;
    const int row_hi   = row_lo + 8;
    const int rowmax_w = q0 + w * 16 + 15;

    float sA[8][4];

    for (int kt = 0; kt < ntile; kt++) {
        const int s0 = kt * BKV;
        const bool active = (s0 <= rowmax_w);

        CP_WAIT1();            // K(kt) arrived   (pending: V(kt))
        __syncthreads();       // K visible to all warps; Qs ready (kt==0)

        // ---- S = Q @ K^T ----
        if (active) {
#pragma unroll
            for (int n = 0; n < 8; n++)
#pragma unroll
                for (int i = 0; i < 4; i++) sA[n][i] = 0.f;
#pragma unroll
            for (int kb = 0; kb < DQK / 8; kb++) {
                const int k0 = kb * 8;
                unsigned a0 = Qs[(w * 16 + g    ) * QSTR + k0 + q    ];
                unsigned a1 = Qs[(w * 16 + g + 8) * QSTR + k0 + q    ];
                unsigned a2 = Qs[(w * 16 + g    ) * QSTR + k0 + q + 4];
                unsigned a3 = Qs[(w * 16 + g + 8) * QSTR + k0 + q + 4];
#pragma unroll
                for (int n = 0; n < 8; n++) {
                    unsigned b0 = Ks[(n * 8 + g) * QSTR + k0 + q    ];
                    unsigned b1 = Ks[(n * 8 + g) * QSTR + k0 + q + 4];
                    mma_tf32(sA[n], a0, a1, a2, a3, b0, b1);
                }
            }
        }
        __syncthreads();       // all warps done reading Ks

        // ---- prefetch K(kt+1) while we do softmax + PV ----
        if (kt + 1 < ntile) {
            const float* base = gKh + (size_t)(s0 + BKV) * DQK;
#pragma unroll
            for (int i = 0; i < 12; i++) {
                int idx = tid + i * 256;
                int r = idx / 48, cw = idx - r * 48;
                CP16(Ks_u + (unsigned)(r * QSTR + cw * 4) * 4u, base + r * DQK + cw * 4);
            }
        }
        CP_COMMIT();           // pending: V(kt), K(kt+1)

        if (active) {
            // ---- scale + causal mask ----
#pragma unroll
            for (int n = 0; n < 8; n++) {
                int c0 = s0 + n * 8 + 2 * q;
                sA[n][0] = (c0     <= row_lo) ? sA[n][0] * QKSCALE : -1.0e30f;
                sA[n][1] = (c0 + 1 <= row_lo) ? sA[n][1] * QKSCALE : -1.0e30f;
                sA[n][2] = (c0     <= row_hi) ? sA[n][2] * QKSCALE : -1.0e30f;
                sA[n][3] = (c0 + 1 <= row_hi) ? sA[n][3] * QKSCALE : -1.0e30f;
            }

            // ---- online softmax in registers ----
            float tm_lo = -1.0e30f, tm_hi = -1.0e30f;
#pragma unroll
            for (int n = 0; n < 8; n++) {
                tm_lo = fmaxf(tm_lo, fmaxf(sA[n][0], sA[n][1]));
                tm_hi = fmaxf(tm_hi, fmaxf(sA[n][2], sA[n][3]));
            }
            tm_lo = fmaxf(tm_lo, __shfl_xor_sync(0xffffffffu, tm_lo, 1));
            tm_lo = fmaxf(tm_lo, __shfl_xor_sync(0xffffffffu, tm_lo, 2));
            tm_hi = fmaxf(tm_hi, __shfl_xor_sync(0xffffffffu, tm_hi, 1));
            tm_hi = fmaxf(tm_hi, __shfl_xor_sync(0xffffffffu, tm_hi, 2));

            float mn_lo = fmaxf(m_lo, tm_lo);
            float mn_hi = fmaxf(m_hi, tm_hi);
            float sc_lo = __expf(m_lo - mn_lo);
            float sc_hi = __expf(m_hi - mn_hi);

            float sum_lo = 0.f, sum_hi = 0.f;
#pragma unroll
            for (int n = 0; n < 8; n++) {
                sA[n][0] = __expf(sA[n][0] - mn_lo);
                sA[n][1] = __expf(sA[n][1] - mn_lo);
                sA[n][2] = __expf(sA[n][2] - mn_hi);
                sA[n][3] = __expf(sA[n][3] - mn_hi);
                sum_lo += sA[n][0] + sA[n][1];
                sum_hi += sA[n][2] + sA[n][3];
            }
            sum_lo += __shfl_xor_sync(0xffffffffu, sum_lo, 1);
            sum_lo += __shfl_xor_sync(0xffffffffu, sum_lo, 2);
            sum_hi += __shfl_xor_sync(0xffffffffu, sum_hi, 1);
            sum_hi += __shfl_xor_sync(0xffffffffu, sum_hi, 2);

            l_lo = l_lo * sc_lo + sum_lo;  m_lo = mn_lo;
            l_hi = l_hi * sc_hi + sum_hi;  m_hi = mn_hi;

#pragma unroll
            for (int n = 0; n < 16; n++) {
                oAcc[n][0] *= sc_lo;  oAcc[n][1] *= sc_lo;
                oAcc[n][2] *= sc_hi;  oAcc[n][3] *= sc_hi;
            }

            // ---- write P (tf32) to warp-private smem ----
            __syncwarp();
#pragma unroll
            for (int n = 0; n < 8; n++) {
                uint2 plo = make_uint2(f2tf(sA[n][0]), f2tf(sA[n][1]));
                uint2 phi = make_uint2(f2tf(sA[n][2]), f2tf(sA[n][3]));
                *(uint2*)&Pw[(g    ) * PSTR + n * 8 + 2 * q] = plo;
                *(uint2*)&Pw[(g + 8) * PSTR + n * 8 + 2 * q] = phi;
            }
            __syncwarp();
        }

        CP_WAIT1();            // V(kt) arrived   (pending: K(kt+1))
        __syncthreads();       // V visible

        // ---- O += P @ V ----
        if (active) {
#pragma unroll
            for (int kb = 0; kb < BKV / 8; kb++) {
                const int k0 = kb * 8;
                unsigned a0 = Pw[(g    ) * PSTR + k0 + q    ];
                unsigned a1 = Pw[(g + 8) * PSTR + k0 + q    ];
                unsigned a2 = Pw[(g    ) * PSTR + k0 + q + 4];
                unsigned a3 = Pw[(g + 8) * PSTR + k0 + q + 4];
#pragma unroll
                for (int n = 0; n < 16; n++) {
                    unsigned b0 = Vs[(k0 + q    ) * VSTR + n * 8 + g];
                    unsigned b1 = Vs[(k0 + q + 4) * VSTR + n * 8 + g];
                    mma_tf32(oAcc[n], a0, a1, a2, a3, b0, b1);
                }
            }
        }
        __syncthreads();       // all warps done reading Vs

        // ---- prefetch V(kt+1) ----
        if (kt + 1 < ntile) {
            const float* base = gVh + (size_t)(s0 + BKV) * VDIM;
#pragma unroll
            for (int i = 0; i < 8; i++) {
                int idx = tid + i * 256;
                int r = idx >> 5, cw = idx & 31;
                CP16(Vs_u + (unsigned)(r * VSTR + cw * 4) * 4u, base + r * VDIM + cw * 4);
            }
        }
        CP_COMMIT();           // pending: K(kt+1), V(kt+1)
    }

    // ---- epilogue: normalize + store ----
    const float il_lo = 1.0f / l_lo;
    const float il_hi = 1.0f / l_hi;
#pragma unroll
    for (int n = 0; n < 16; n++) {
        int col = h * VDIM + n * 8 + 2 * q;
        float2 vlo = make_float2(oAcc[n][0] * il_lo, oAcc[n][1] * il_lo);
        float2 vhi = make_float2(oAcc[n][2] * il_hi, oAcc[n][3] * il_hi);
        *(float2*)&out[(size_t)row_lo * (HH * VDIM) + col] = vlo;
        *(float2*)&out[(size_t)row_hi * (HH * VDIM) + col] = vhi;
    }
}

// ---------------------------------------------------------------------------
extern "C" void kernel_launch(void* const* d_in, const int* in_sizes, int n_in,
                              void* d_out, int out_size)
{
    const float* query = (const float*)d_in[0];  // (T, H, 192)
    const float* kc    = (const float*)d_in[1];  // (T, 512)
    const float* kpe   = (const float*)d_in[2];  // (T, 64)
    const float* wkv   = (const float*)d_in[3];  // (512, 4096)
    const float* wuv   = (const float*)d_in[4];  // (16, 512, 128)
    float* out = (float*)d_out;                  // (T, 2048)

    rope_fill_kernel<<<(HH * TT * ROPE + 255) / 256, 256>>>(kpe);
    kv_gemm_kernel<<<dim3(64, 32), 256>>>(kc, wkv, wuv);

    size_t smem = (size_t)(BQ * QSTR + BKV * QSTR + BKV * VSTR + NWARP * 16 * PSTR)
                  * sizeof(unsigned);   // 220,160 B
    cudaFuncSetAttribute(attn_kernel,
                         cudaFuncAttributeMaxDynamicSharedMemorySize, (int)smem);
    attn_kernel<<<dim3(TT / BQ, HH), 256, smem>>>(query, out);
}